// round 2
// baseline (speedup 1.0000x reference)
#include <cuda_runtime.h>
#include <cstdint>

#define BTc 16
#define Nc 1024
#define Dc 128
#define Hc 8
#define HDc 16
#define Mc (BTc*Nc)   // 16384 rows

// ---- scratch (no allocations allowed) ----
__device__ float g_q[(size_t)BTc*Hc*Nc*HDc];   // 8 MB, head-major, pre-scaled by log2e/4
__device__ float g_k[(size_t)BTc*Hc*Nc*HDc];   // 8 MB
__device__ float g_v[(size_t)BTc*Hc*Nc*HDc];   // 8 MB
__device__ float g_ctx[(size_t)Mc*Dc];         // 8 MB

// ---- packed f32x2 helpers (FFMA2 is PTX-only on sm_103a) ----
typedef unsigned long long f2_t;

__device__ __forceinline__ f2_t f2_mul(f2_t a, f2_t b){ f2_t r; asm("mul.rn.f32x2 %0,%1,%2;":"=l"(r):"l"(a),"l"(b)); return r; }
__device__ __forceinline__ f2_t f2_fma(f2_t a, f2_t b, f2_t c){ f2_t r; asm("fma.rn.f32x2 %0,%1,%2,%3;":"=l"(r):"l"(a),"l"(b),"l"(c)); return r; }
__device__ __forceinline__ f2_t f2_add(f2_t a, f2_t b){ f2_t r; asm("add.rn.f32x2 %0,%1,%2;":"=l"(r):"l"(a),"l"(b)); return r; }
__device__ __forceinline__ f2_t f2_pack(float lo, float hi){ f2_t r; asm("mov.b64 %0,{%1,%2};":"=l"(r):"f"(lo),"f"(hi)); return r; }
__device__ __forceinline__ void f2_unpack(f2_t a, float& lo, float& hi){ asm("mov.b64 {%0,%1},%2;":"=f"(lo),"=f"(hi):"l"(a)); }
__device__ __forceinline__ float fast_ex2(float x){ float r; asm("ex2.approx.f32 %0,%1;":"=f"(r):"f"(x)); return r; }

// ============================================================
// GEMM tile: 128 rows x 128 cols, K=128.  out = X @ W^T  (torch Linear)
// smem: Xs[128][132], Ws[128][132] (pad 132 -> <=2-way conflicts)
// thread (tx=tid&15, ty=tid>>4): rows ty*8+i, col pairs (tx+32t, tx+32t+16)
// ============================================================
__device__ __forceinline__ void gemm_tile(const float* __restrict__ Xg,
                                          const float* __restrict__ Wg,
                                          float* Xs, float* Ws,
                                          f2_t acc2[8][4], int m0, int tid)
{
    #pragma unroll
    for (int it = 0; it < 16; ++it) {
        int idx = it*256 + tid;
        int m = idx >> 5, k4 = idx & 31;
        *(float4*)(Xs + m*132 + k4*4) = *(const float4*)(Xg + (size_t)(m0+m)*128 + k4*4);
        *(float4*)(Ws + m*132 + k4*4) = *(const float4*)(Wg + (size_t)m*128 + k4*4);
    }
    __syncthreads();

    int tx = tid & 15, ty = tid >> 4;
    #pragma unroll
    for (int i = 0; i < 8; ++i)
        #pragma unroll
        for (int t = 0; t < 4; ++t) acc2[i][t] = 0ULL;

    #pragma unroll 4
    for (int k = 0; k < 128; ++k) {
        f2_t a2[8], b2[4];
        #pragma unroll
        for (int i = 0; i < 8; ++i) {
            float a = Xs[(ty*8+i)*132 + k];
            a2[i] = f2_pack(a, a);
        }
        #pragma unroll
        for (int t = 0; t < 4; ++t) {
            float blo = Ws[(tx + 32*t)*132 + k];
            float bhi = Ws[(tx + 32*t + 16)*132 + k];
            b2[t] = f2_pack(blo, bhi);
        }
        #pragma unroll
        for (int i = 0; i < 8; ++i)
            #pragma unroll
            for (int t = 0; t < 4; ++t)
                acc2[i][t] = f2_fma(a2[i], b2[t], acc2[i][t]);
    }
}

// ============================================================
// QKV projection: grid (128, 3), 256 thr.  Writes head-major (bt,h,n,hd).
// Q is pre-scaled by log2(e)/4 so attention uses bare ex2.
// ============================================================
__global__ void __launch_bounds__(256) proj_qkv_kernel(
    const float* __restrict__ x,
    const float* __restrict__ Wq, const float* __restrict__ bq,
    const float* __restrict__ Wk, const float* __restrict__ bk,
    const float* __restrict__ Wv, const float* __restrict__ bv)
{
    extern __shared__ float sm[];
    float* Xs = sm;
    float* Ws = sm + 128*132;

    int sel = blockIdx.y;
    const float* W    = (sel == 0) ? Wq : (sel == 1) ? Wk : Wv;
    const float* bias = (sel == 0) ? bq : (sel == 1) ? bk : bv;
    float*       out  = (sel == 0) ? g_q : (sel == 1) ? g_k : g_v;
    float scale = (sel == 0) ? (0.25f * 1.4426950408889634f) : 1.0f;

    int m0 = blockIdx.x * 128;
    f2_t acc2[8][4];
    gemm_tile(x, W, Xs, Ws, acc2, m0, threadIdx.x);

    int tx = threadIdx.x & 15, ty = threadIdx.x >> 4;
    int bt = m0 / Nc;          // 128-row tile never crosses bt (N=1024)
    int nbase = m0 % Nc;
    #pragma unroll
    for (int i = 0; i < 8; ++i) {
        int n = nbase + ty*8 + i;
        #pragma unroll
        for (int t = 0; t < 4; ++t) {
            float lo, hi; f2_unpack(acc2[i][t], lo, hi);
            int j0 = tx + 32*t, j1 = j0 + 16;
            float v0 = (lo + bias[j0]) * scale;
            float v1 = (hi + bias[j1]) * scale;
            out[(((size_t)bt*Hc + (j0 >> 4))*Nc + n)*HDc + (j0 & 15)] = v0;
            out[(((size_t)bt*Hc + (j1 >> 4))*Nc + n)*HDc + (j1 & 15)] = v1;
        }
    }
}

// ============================================================
// O projection: reads g_ctx, writes final output (bt,n,d) directly.
// ============================================================
__global__ void __launch_bounds__(256) proj_o_kernel(
    const float* __restrict__ Wo, const float* __restrict__ bo,
    float* __restrict__ out)
{
    extern __shared__ float sm[];
    float* Xs = sm;
    float* Ws = sm + 128*132;

    int m0 = blockIdx.x * 128;
    f2_t acc2[8][4];
    gemm_tile(g_ctx, Wo, Xs, Ws, acc2, m0, threadIdx.x);

    int tx = threadIdx.x & 15, ty = threadIdx.x >> 4;
    #pragma unroll
    for (int i = 0; i < 8; ++i) {
        size_t m = m0 + ty*8 + i;
        #pragma unroll
        for (int t = 0; t < 4; ++t) {
            float lo, hi; f2_unpack(acc2[i][t], lo, hi);
            int j0 = tx + 32*t, j1 = j0 + 16;
            out[m*Dc + j0] = lo + bo[j0];
            out[m*Dc + j1] = hi + bo[j1];
        }
    }
}

// ============================================================
// Fused attention: one CTA = one (bt, h, 256-row block).
// p = exp2(q'.k) * adj   (q' pre-scaled; no max subtraction needed:
// |score*log2e| <= ~12 over the whole problem -> fp32-safe)
// ctx = (sum_c p*v) / (sum_c p)
// K,V slab (1024x16 fp32 each = 128KB) lives in smem; thread <-> row;
// K/V rows are warp-broadcast LDS; adj streamed from L2.
// grid ordered so 32 consecutive CTAs share bt -> adj L2-resident.
// ============================================================
__global__ void __launch_bounds__(256) attn_kernel(const float* __restrict__ adj)
{
    extern __shared__ float sm[];
    float* Ks = sm;              // [1024][16]
    float* Vs = sm + Nc*HDc;     // [1024][16]

    int bid = blockIdx.x;
    int bt = bid >> 5;
    int sub = bid & 31;
    int rowblk = sub >> 3;
    int h = sub & 7;
    int slab = bt*Hc + h;

    const float* kg = g_k + (size_t)slab*Nc*HDc;
    const float* vg = g_v + (size_t)slab*Nc*HDc;
    for (int i = threadIdx.x; i < Nc*HDc/4; i += 256) {
        ((float4*)Ks)[i] = ((const float4*)kg)[i];
        ((float4*)Vs)[i] = ((const float4*)vg)[i];
    }
    __syncthreads();

    int r = rowblk*256 + threadIdx.x;
    const float* qp = g_q + ((size_t)slab*Nc + r)*HDc;

    f2_t q2[8];
    #pragma unroll
    for (int j = 0; j < 4; ++j) {
        float4 f = *(const float4*)(qp + j*4);
        q2[2*j]   = f2_pack(f.x, f.y);
        q2[2*j+1] = f2_pack(f.z, f.w);
    }

    f2_t acc2[8];
    #pragma unroll
    for (int j = 0; j < 8; ++j) acc2[j] = 0ULL;
    float sum = 0.0f;

    const float* adjrow = adj + ((size_t)bt*Nc + r)*Nc;
    float4 av = *(const float4*)adjrow;

    for (int c4 = 0; c4 < Nc; c4 += 4) {
        int nxt = (c4 + 4 < Nc) ? (c4 + 4) : 0;
        float4 nav = *(const float4*)(adjrow + nxt);   // prefetch
        float aarr[4] = {av.x, av.y, av.z, av.w};

        #pragma unroll
        for (int u = 0; u < 4; ++u) {
            int c = c4 + u;
            const ulonglong2* kr = (const ulonglong2*)(Ks + c*HDc);
            ulonglong2 k0 = kr[0], k1 = kr[1], k2 = kr[2], k3 = kr[3];

            // q . k  via 4 independent f32x2 chains (hide FFMA latency)
            f2_t d0 = f2_mul(q2[0], k0.x);
            f2_t d1 = f2_mul(q2[1], k0.y);
            f2_t d2 = f2_mul(q2[2], k1.x);
            f2_t d3 = f2_mul(q2[3], k1.y);
            d0 = f2_fma(q2[4], k2.x, d0);
            d1 = f2_fma(q2[5], k2.y, d1);
            d2 = f2_fma(q2[6], k3.x, d2);
            d3 = f2_fma(q2[7], k3.y, d3);
            d0 = f2_add(d0, d1);
            d2 = f2_add(d2, d3);
            d0 = f2_add(d0, d2);
            float lo, hi; f2_unpack(d0, lo, hi);
            float s = lo + hi;                    // already in log2 domain

            float p = fast_ex2(s) * aarr[u];      // exp(score) * adj  (MUFU pipe)
            sum += p;
            f2_t pp = f2_pack(p, p);

            const ulonglong2* vr = (const ulonglong2*)(Vs + c*HDc);
            ulonglong2 v0 = vr[0], v1 = vr[1], v2 = vr[2], v3 = vr[3];
            acc2[0] = f2_fma(pp, v0.x, acc2[0]);
            acc2[1] = f2_fma(pp, v0.y, acc2[1]);
            acc2[2] = f2_fma(pp, v1.x, acc2[2]);
            acc2[3] = f2_fma(pp, v1.y, acc2[3]);
            acc2[4] = f2_fma(pp, v2.x, acc2[4]);
            acc2[5] = f2_fma(pp, v2.y, acc2[5]);
            acc2[6] = f2_fma(pp, v3.x, acc2[6]);
            acc2[7] = f2_fma(pp, v3.y, acc2[7]);
        }
        av = nav;
    }

    float inv = 1.0f / sum;
    float* outp = g_ctx + ((size_t)bt*Nc + r)*Dc + h*HDc;
    #pragma unroll
    for (int j = 0; j < 4; ++j) {
        float lo0, hi0, lo1, hi1;
        f2_unpack(acc2[2*j],   lo0, hi0);
        f2_unpack(acc2[2*j+1], lo1, hi1);
        float4 o = make_float4(lo0*inv, hi0*inv, lo1*inv, hi1*inv);
        *(float4*)(outp + j*4) = o;
    }
}

// ============================================================
extern "C" void kernel_launch(void* const* d_in, const int* in_sizes, int n_in,
                              void* d_out, int out_size)
{
    const float* x   = (const float*)d_in[0];
    const float* adj = (const float*)d_in[1];
    const float* Wq  = (const float*)d_in[2];
    const float* bq  = (const float*)d_in[3];
    const float* Wk  = (const float*)d_in[4];
    const float* bk  = (const float*)d_in[5];
    const float* Wv  = (const float*)d_in[6];
    const float* bv  = (const float*)d_in[7];
    const float* Wo  = (const float*)d_in[8];
    const float* bo  = (const float*)d_in[9];
    float* out = (float*)d_out;

    const int smem_proj = 2 * 128 * 132 * sizeof(float);   // 135168
    const int smem_attn = 2 * Nc * HDc * sizeof(float);    // 131072
    cudaFuncSetAttribute(proj_qkv_kernel, cudaFuncAttributeMaxDynamicSharedMemorySize, smem_proj);
    cudaFuncSetAttribute(proj_o_kernel,   cudaFuncAttributeMaxDynamicSharedMemorySize, smem_proj);
    cudaFuncSetAttribute(attn_kernel,     cudaFuncAttributeMaxDynamicSharedMemorySize, smem_attn);

    dim3 gqkv(Mc/128, 3);
    proj_qkv_kernel<<<gqkv, 256, smem_proj>>>(x, Wq, bq, Wk, bk, Wv, bv);
    attn_kernel<<<BTc*Hc*4, 256, smem_attn>>>(adj);
    proj_o_kernel<<<Mc/128, 256, smem_proj>>>(Wo, bo, out);
}

// round 3
// speedup vs baseline: 1.4331x; 1.4331x over previous
#include <cuda_runtime.h>
#include <cstdint>

#define BTc 16
#define Nc 1024
#define Dc 128
#define Hc 8
#define HDc 16
#define Mc (BTc*Nc)   // 16384 rows

// ---- scratch (no allocations allowed) ----
__device__ float g_q[(size_t)BTc*Hc*Nc*HDc];   // 8 MB, head-major, pre-scaled by log2e/4
__device__ float g_k[(size_t)BTc*Hc*Nc*HDc];   // 8 MB
__device__ float g_v[(size_t)BTc*Hc*Nc*HDc];   // 8 MB
__device__ float g_ctx[(size_t)Mc*Dc];         // 8 MB

// ---- packed f32x2 helpers (FFMA2 is PTX-only on sm_103a) ----
typedef unsigned long long f2_t;

__device__ __forceinline__ f2_t f2_mul(f2_t a, f2_t b){ f2_t r; asm("mul.rn.f32x2 %0,%1,%2;":"=l"(r):"l"(a),"l"(b)); return r; }
__device__ __forceinline__ f2_t f2_fma(f2_t a, f2_t b, f2_t c){ f2_t r; asm("fma.rn.f32x2 %0,%1,%2,%3;":"=l"(r):"l"(a),"l"(b),"l"(c)); return r; }
__device__ __forceinline__ f2_t f2_add(f2_t a, f2_t b){ f2_t r; asm("add.rn.f32x2 %0,%1,%2;":"=l"(r):"l"(a),"l"(b)); return r; }
__device__ __forceinline__ f2_t f2_pack(float lo, float hi){ f2_t r; asm("mov.b64 %0,{%1,%2};":"=l"(r):"f"(lo),"f"(hi)); return r; }
__device__ __forceinline__ void f2_unpack(f2_t a, float& lo, float& hi){ asm("mov.b64 {%0,%1},%2;":"=f"(lo),"=f"(hi):"l"(a)); }
__device__ __forceinline__ float fast_ex2(float x){ float r; asm("ex2.approx.f32 %0,%1;":"=f"(r):"f"(x)); return r; }

// ============================================================
// GEMM tile: 128 rows x 128 cols, K=128.  out = X @ W^T  (torch Linear)
// ============================================================
__device__ __forceinline__ void gemm_tile(const float* __restrict__ Xg,
                                          const float* __restrict__ Wg,
                                          float* Xs, float* Ws,
                                          f2_t acc2[8][4], int m0, int tid)
{
    #pragma unroll
    for (int it = 0; it < 16; ++it) {
        int idx = it*256 + tid;
        int m = idx >> 5, k4 = idx & 31;
        *(float4*)(Xs + m*132 + k4*4) = *(const float4*)(Xg + (size_t)(m0+m)*128 + k4*4);
        *(float4*)(Ws + m*132 + k4*4) = *(const float4*)(Wg + (size_t)m*128 + k4*4);
    }
    __syncthreads();

    int tx = tid & 15, ty = tid >> 4;
    #pragma unroll
    for (int i = 0; i < 8; ++i)
        #pragma unroll
        for (int t = 0; t < 4; ++t) acc2[i][t] = 0ULL;

    #pragma unroll 4
    for (int k = 0; k < 128; ++k) {
        f2_t a2[8], b2[4];
        #pragma unroll
        for (int i = 0; i < 8; ++i) {
            float a = Xs[(ty*8+i)*132 + k];
            a2[i] = f2_pack(a, a);
        }
        #pragma unroll
        for (int t = 0; t < 4; ++t) {
            float blo = Ws[(tx + 32*t)*132 + k];
            float bhi = Ws[(tx + 32*t + 16)*132 + k];
            b2[t] = f2_pack(blo, bhi);
        }
        #pragma unroll
        for (int i = 0; i < 8; ++i)
            #pragma unroll
            for (int t = 0; t < 4; ++t)
                acc2[i][t] = f2_fma(a2[i], b2[t], acc2[i][t]);
    }
}

// ============================================================
// QKV projection: grid (128, 3), 256 thr.  Writes head-major (bt,h,n,hd).
// ============================================================
__global__ void __launch_bounds__(256) proj_qkv_kernel(
    const float* __restrict__ x,
    const float* __restrict__ Wq, const float* __restrict__ bq,
    const float* __restrict__ Wk, const float* __restrict__ bk,
    const float* __restrict__ Wv, const float* __restrict__ bv)
{
    extern __shared__ float sm[];
    float* Xs = sm;
    float* Ws = sm + 128*132;

    int sel = blockIdx.y;
    const float* W    = (sel == 0) ? Wq : (sel == 1) ? Wk : Wv;
    const float* bias = (sel == 0) ? bq : (sel == 1) ? bk : bv;
    float*       out  = (sel == 0) ? g_q : (sel == 1) ? g_k : g_v;
    float scale = (sel == 0) ? (0.25f * 1.4426950408889634f) : 1.0f;

    int m0 = blockIdx.x * 128;
    f2_t acc2[8][4];
    gemm_tile(x, W, Xs, Ws, acc2, m0, threadIdx.x);

    int tx = threadIdx.x & 15, ty = threadIdx.x >> 4;
    int bt = m0 / Nc;
    int nbase = m0 % Nc;
    #pragma unroll
    for (int i = 0; i < 8; ++i) {
        int n = nbase + ty*8 + i;
        #pragma unroll
        for (int t = 0; t < 4; ++t) {
            float lo, hi; f2_unpack(acc2[i][t], lo, hi);
            int j0 = tx + 32*t, j1 = j0 + 16;
            float v0 = (lo + bias[j0]) * scale;
            float v1 = (hi + bias[j1]) * scale;
            out[(((size_t)bt*Hc + (j0 >> 4))*Nc + n)*HDc + (j0 & 15)] = v0;
            out[(((size_t)bt*Hc + (j1 >> 4))*Nc + n)*HDc + (j1 & 15)] = v1;
        }
    }
}

// ============================================================
// O projection
// ============================================================
__global__ void __launch_bounds__(256) proj_o_kernel(
    const float* __restrict__ Wo, const float* __restrict__ bo,
    float* __restrict__ out)
{
    extern __shared__ float sm[];
    float* Xs = sm;
    float* Ws = sm + 128*132;

    int m0 = blockIdx.x * 128;
    f2_t acc2[8][4];
    gemm_tile(g_ctx, Wo, Xs, Ws, acc2, m0, threadIdx.x);

    int tx = threadIdx.x & 15, ty = threadIdx.x >> 4;
    #pragma unroll
    for (int i = 0; i < 8; ++i) {
        size_t m = m0 + ty*8 + i;
        #pragma unroll
        for (int t = 0; t < 4; ++t) {
            float lo, hi; f2_unpack(acc2[i][t], lo, hi);
            int j0 = tx + 32*t, j1 = j0 + 16;
            out[m*Dc + j0] = lo + bo[j0];
            out[m*Dc + j1] = hi + bo[j1];
        }
    }
}

// ============================================================
// Fused attention v2: one CTA = one (bt, h) slab (ALL 1024 rows).
// 256 threads, R=4 rows/thread (rows 4t..4t+3) -> K/V broadcast LDS
// amortized over 4 rows (0.25 wf/cell instead of 1.0).
// adj: staged through smem in transposed [8][1028] chunks, loaded
// coalesced with a register-prefetch software pipeline.
// grid = 128 (one CTA per SM, single wave).
// ============================================================
#define CHUNK 8
#define NCHUNK (Nc/CHUNK)         // 128
#define APAD 1028                 // stride: %32==4 (conflict-free STS), *4%16==0 (aligned LDS.128)

__global__ void __launch_bounds__(256,1) attn_kernel(const float* __restrict__ adj)
{
    extern __shared__ float sm[];
    float* Ks = sm;                       // [1024][16]
    float* Vs = sm + Nc*HDc;              // [1024][16]
    float* As = sm + 2*Nc*HDc;            // [CHUNK][APAD] transposed adj chunk

    int bt = blockIdx.x >> 3;
    int h  = blockIdx.x & 7;
    int slab = bt*Hc + h;
    int t = threadIdx.x;

    // ---- load K,V slab (coalesced) ----
    const float* kg = g_k + (size_t)slab*Nc*HDc;
    const float* vg = g_v + (size_t)slab*Nc*HDc;
    #pragma unroll
    for (int i = t; i < Nc*HDc/4; i += 256) {
        ((float4*)Ks)[i] = ((const float4*)kg)[i];
        ((float4*)Vs)[i] = ((const float4*)vg)[i];
    }

    // ---- load q for my 4 rows (pre-scaled by log2e/4) ----
    int r0 = 4*t;
    f2_t q2[4][8];
    const float* qp = g_q + ((size_t)slab*Nc + r0)*HDc;
    #pragma unroll
    for (int rr = 0; rr < 4; ++rr)
        #pragma unroll
        for (int j = 0; j < 4; ++j) {
            float4 f = *(const float4*)(qp + rr*HDc + j*4);
            q2[rr][2*j]   = f2_pack(f.x, f.y);
            q2[rr][2*j+1] = f2_pack(f.z, f.w);
        }

    f2_t acc2[4][8];
    #pragma unroll
    for (int rr = 0; rr < 4; ++rr)
        #pragma unroll
        for (int j = 0; j < 8; ++j) acc2[rr][j] = 0ULL;
    float sum[4] = {0.f, 0.f, 0.f, 0.f};

    // adj base for this bt; per-thread fixed (row, colgroup) slot inside a chunk
    const float* ag = adj + (size_t)bt*Nc*Nc;
    // element e = it*256 + t covers chunk tile [1024 rows][8 cols] as float4s:
    // row = e>>1, colgroup cq = e&1 (cols 4cq..4cq+3)
    // prefetch chunk 0
    float4 pf[8];
    #pragma unroll
    for (int it = 0; it < 8; ++it) {
        int e = it*256 + t;
        int r = e >> 1, cq = e & 1;
        pf[it] = *(const float4*)(ag + (size_t)r*Nc + 4*cq);
    }
    __syncthreads();   // K,V ready

    for (int chunk = 0; chunk < NCHUNK; ++chunk) {
        // ---- store prefetched chunk transposed into As (conflict-free) ----
        #pragma unroll
        for (int it = 0; it < 8; ++it) {
            int e = it*256 + t;
            int r = e >> 1, cq = e & 1;
            As[(4*cq+0)*APAD + r] = pf[it].x;
            As[(4*cq+1)*APAD + r] = pf[it].y;
            As[(4*cq+2)*APAD + r] = pf[it].z;
            As[(4*cq+3)*APAD + r] = pf[it].w;
        }
        // ---- prefetch next chunk (latency hidden behind compute) ----
        int nchunk = (chunk+1 < NCHUNK) ? (chunk+1) : 0;
        const float* agn = ag + nchunk*CHUNK;
        #pragma unroll
        for (int it = 0; it < 8; ++it) {
            int e = it*256 + t;
            int r = e >> 1, cq = e & 1;
            pf[it] = *(const float4*)(agn + (size_t)r*Nc + 4*cq);
        }
        __syncthreads();   // As populated

        int c0 = chunk*CHUNK;
        #pragma unroll 2
        for (int lc = 0; lc < CHUNK; ++lc) {
            int c = c0 + lc;
            // K,V rows (broadcast; reused across my 4 rows)
            const ulonglong2* kr = (const ulonglong2*)(Ks + c*HDc);
            ulonglong2 k0 = kr[0], k1 = kr[1], k2 = kr[2], k3 = kr[3];
            const ulonglong2* vr = (const ulonglong2*)(Vs + c*HDc);
            ulonglong2 v0 = vr[0], v1 = vr[1], v2 = vr[2], v3 = vr[3];
            // adj for my 4 rows at column c: one conflict-free LDS.128
            float4 a4 = *(const float4*)(As + lc*APAD + r0);
            float aarr[4] = {a4.x, a4.y, a4.z, a4.w};

            #pragma unroll
            for (int rr = 0; rr < 4; ++rr) {
                f2_t d0 = f2_mul(q2[rr][0], k0.x);
                f2_t d1 = f2_mul(q2[rr][1], k0.y);
                f2_t d2 = f2_mul(q2[rr][2], k1.x);
                f2_t d3 = f2_mul(q2[rr][3], k1.y);
                d0 = f2_fma(q2[rr][4], k2.x, d0);
                d1 = f2_fma(q2[rr][5], k2.y, d1);
                d2 = f2_fma(q2[rr][6], k3.x, d2);
                d3 = f2_fma(q2[rr][7], k3.y, d3);
                d0 = f2_add(d0, d1);
                d2 = f2_add(d2, d3);
                d0 = f2_add(d0, d2);
                float lo, hi; f2_unpack(d0, lo, hi);
                float s = lo + hi;                 // log2-domain score

                float p = fast_ex2(s) * aarr[rr];  // MUFU pipe
                sum[rr] += p;
                f2_t pp = f2_pack(p, p);

                acc2[rr][0] = f2_fma(pp, v0.x, acc2[rr][0]);
                acc2[rr][1] = f2_fma(pp, v0.y, acc2[rr][1]);
                acc2[rr][2] = f2_fma(pp, v1.x, acc2[rr][2]);
                acc2[rr][3] = f2_fma(pp, v1.y, acc2[rr][3]);
                acc2[rr][4] = f2_fma(pp, v2.x, acc2[rr][4]);
                acc2[rr][5] = f2_fma(pp, v2.y, acc2[rr][5]);
                acc2[rr][6] = f2_fma(pp, v3.x, acc2[rr][6]);
                acc2[rr][7] = f2_fma(pp, v3.y, acc2[rr][7]);
            }
        }
        __syncthreads();   // done reading As before next overwrite
    }

    // ---- write context ----
    #pragma unroll
    for (int rr = 0; rr < 4; ++rr) {
        float inv = 1.0f / sum[rr];
        float* outp = g_ctx + ((size_t)bt*Nc + r0 + rr)*Dc + h*HDc;
        #pragma unroll
        for (int j = 0; j < 4; ++j) {
            float lo0, hi0, lo1, hi1;
            f2_unpack(acc2[rr][2*j],   lo0, hi0);
            f2_unpack(acc2[rr][2*j+1], lo1, hi1);
            *(float4*)(outp + j*4) = make_float4(lo0*inv, hi0*inv, lo1*inv, hi1*inv);
        }
    }
}

// ============================================================
extern "C" void kernel_launch(void* const* d_in, const int* in_sizes, int n_in,
                              void* d_out, int out_size)
{
    const float* x   = (const float*)d_in[0];
    const float* adj = (const float*)d_in[1];
    const float* Wq  = (const float*)d_in[2];
    const float* bq  = (const float*)d_in[3];
    const float* Wk  = (const float*)d_in[4];
    const float* bk  = (const float*)d_in[5];
    const float* Wv  = (const float*)d_in[6];
    const float* bv  = (const float*)d_in[7];
    const float* Wo  = (const float*)d_in[8];
    const float* bo  = (const float*)d_in[9];
    float* out = (float*)d_out;

    const int smem_proj = 2 * 128 * 132 * sizeof(float);                  // 135168
    const int smem_attn = (2*Nc*HDc + CHUNK*APAD) * sizeof(float);        // 163968
    cudaFuncSetAttribute(proj_qkv_kernel, cudaFuncAttributeMaxDynamicSharedMemorySize, smem_proj);
    cudaFuncSetAttribute(proj_o_kernel,   cudaFuncAttributeMaxDynamicSharedMemorySize, smem_proj);
    cudaFuncSetAttribute(attn_kernel,     cudaFuncAttributeMaxDynamicSharedMemorySize, smem_attn);

    dim3 gqkv(Mc/128, 3);
    proj_qkv_kernel<<<gqkv, 256, smem_proj>>>(x, Wq, bq, Wk, bk, Wv, bv);
    attn_kernel<<<BTc*Hc, 256, smem_attn>>>(adj);
    proj_o_kernel<<<Mc/128, 256, smem_proj>>>(Wo, bo, out);
}

// round 4
// speedup vs baseline: 1.4645x; 1.0219x over previous
#include <cuda_runtime.h>
#include <cstdint>

#define BTc 16
#define Nc 1024
#define Dc 128
#define Hc 8
#define HDc 16
#define Mc (BTc*Nc)   // 16384 rows

// ---- scratch (no allocations allowed) ----
__device__ float g_q[(size_t)BTc*Hc*Nc*HDc];   // 8 MB, head-major, pre-scaled by log2e/4
__device__ float g_k[(size_t)BTc*Hc*Nc*HDc];   // 8 MB
__device__ float g_v[(size_t)BTc*Hc*Nc*HDc];   // 8 MB
__device__ float g_ctx[(size_t)Mc*Dc];         // 8 MB

// ---- packed f32x2 helpers (FFMA2 is PTX-only on sm_103a) ----
typedef unsigned long long f2_t;

__device__ __forceinline__ f2_t f2_mul(f2_t a, f2_t b){ f2_t r; asm("mul.rn.f32x2 %0,%1,%2;":"=l"(r):"l"(a),"l"(b)); return r; }
__device__ __forceinline__ f2_t f2_fma(f2_t a, f2_t b, f2_t c){ f2_t r; asm("fma.rn.f32x2 %0,%1,%2,%3;":"=l"(r):"l"(a),"l"(b),"l"(c)); return r; }
__device__ __forceinline__ f2_t f2_add(f2_t a, f2_t b){ f2_t r; asm("add.rn.f32x2 %0,%1,%2;":"=l"(r):"l"(a),"l"(b)); return r; }
__device__ __forceinline__ f2_t f2_pack(float lo, float hi){ f2_t r; asm("mov.b64 %0,{%1,%2};":"=l"(r):"f"(lo),"f"(hi)); return r; }
__device__ __forceinline__ void f2_unpack(f2_t a, float& lo, float& hi){ asm("mov.b64 {%0,%1},%2;":"=f"(lo),"=f"(hi):"l"(a)); }
__device__ __forceinline__ float fast_ex2(float x){ float r; asm("ex2.approx.f32 %0,%1;":"=f"(r):"f"(x)); return r; }

// ============================================================
// GEMM tile: 128 rows x 128 cols, K=128.  out = X @ W^T  (torch Linear)
// ============================================================
__device__ __forceinline__ void gemm_tile(const float* __restrict__ Xg,
                                          const float* __restrict__ Wg,
                                          float* Xs, float* Ws,
                                          f2_t acc2[8][4], int m0, int tid)
{
    #pragma unroll
    for (int it = 0; it < 16; ++it) {
        int idx = it*256 + tid;
        int m = idx >> 5, k4 = idx & 31;
        *(float4*)(Xs + m*132 + k4*4) = *(const float4*)(Xg + (size_t)(m0+m)*128 + k4*4);
        *(float4*)(Ws + m*132 + k4*4) = *(const float4*)(Wg + (size_t)m*128 + k4*4);
    }
    __syncthreads();

    int tx = tid & 15, ty = tid >> 4;
    #pragma unroll
    for (int i = 0; i < 8; ++i)
        #pragma unroll
        for (int t = 0; t < 4; ++t) acc2[i][t] = 0ULL;

    #pragma unroll 4
    for (int k = 0; k < 128; ++k) {
        f2_t a2[8], b2[4];
        #pragma unroll
        for (int i = 0; i < 8; ++i) {
            float a = Xs[(ty*8+i)*132 + k];
            a2[i] = f2_pack(a, a);
        }
        #pragma unroll
        for (int t = 0; t < 4; ++t) {
            float blo = Ws[(tx + 32*t)*132 + k];
            float bhi = Ws[(tx + 32*t + 16)*132 + k];
            b2[t] = f2_pack(blo, bhi);
        }
        #pragma unroll
        for (int i = 0; i < 8; ++i)
            #pragma unroll
            for (int t = 0; t < 4; ++t)
                acc2[i][t] = f2_fma(a2[i], b2[t], acc2[i][t]);
    }
}

// ============================================================
// QKV projection: grid (128, 3), 256 thr.  Writes head-major (bt,h,n,hd).
// ============================================================
__global__ void __launch_bounds__(256) proj_qkv_kernel(
    const float* __restrict__ x,
    const float* __restrict__ Wq, const float* __restrict__ bq,
    const float* __restrict__ Wk, const float* __restrict__ bk,
    const float* __restrict__ Wv, const float* __restrict__ bv)
{
    extern __shared__ float sm[];
    float* Xs = sm;
    float* Ws = sm + 128*132;

    int sel = blockIdx.y;
    const float* W    = (sel == 0) ? Wq : (sel == 1) ? Wk : Wv;
    const float* bias = (sel == 0) ? bq : (sel == 1) ? bk : bv;
    float*       out  = (sel == 0) ? g_q : (sel == 1) ? g_k : g_v;
    float scale = (sel == 0) ? (0.25f * 1.4426950408889634f) : 1.0f;

    int m0 = blockIdx.x * 128;
    f2_t acc2[8][4];
    gemm_tile(x, W, Xs, Ws, acc2, m0, threadIdx.x);

    int tx = threadIdx.x & 15, ty = threadIdx.x >> 4;
    int bt = m0 / Nc;
    int nbase = m0 % Nc;
    #pragma unroll
    for (int i = 0; i < 8; ++i) {
        int n = nbase + ty*8 + i;
        #pragma unroll
        for (int t = 0; t < 4; ++t) {
            float lo, hi; f2_unpack(acc2[i][t], lo, hi);
            int j0 = tx + 32*t, j1 = j0 + 16;
            float v0 = (lo + bias[j0]) * scale;
            float v1 = (hi + bias[j1]) * scale;
            out[(((size_t)bt*Hc + (j0 >> 4))*Nc + n)*HDc + (j0 & 15)] = v0;
            out[(((size_t)bt*Hc + (j1 >> 4))*Nc + n)*HDc + (j1 & 15)] = v1;
        }
    }
}

// ============================================================
// O projection
// ============================================================
__global__ void __launch_bounds__(256) proj_o_kernel(
    const float* __restrict__ Wo, const float* __restrict__ bo,
    float* __restrict__ out)
{
    extern __shared__ float sm[];
    float* Xs = sm;
    float* Ws = sm + 128*132;

    int m0 = blockIdx.x * 128;
    f2_t acc2[8][4];
    gemm_tile(g_ctx, Wo, Xs, Ws, acc2, m0, threadIdx.x);

    int tx = threadIdx.x & 15, ty = threadIdx.x >> 4;
    #pragma unroll
    for (int i = 0; i < 8; ++i) {
        size_t m = m0 + ty*8 + i;
        #pragma unroll
        for (int t = 0; t < 4; ++t) {
            float lo, hi; f2_unpack(acc2[i][t], lo, hi);
            int j0 = tx + 32*t, j1 = j0 + 16;
            out[m*Dc + j0] = lo + bo[j0];
            out[m*Dc + j1] = hi + bo[j1];
        }
    }
}

// ============================================================
// Fused attention v3: one CTA = one (bt, h) slab, 256 thr, R=4 rows/thr.
// Changes vs v2:
//  - adj staging tile DOUBLE-BUFFERED -> 1 barrier per chunk (128 total)
//  - 9-op f32x2 dot product (2 accumulator chains) instead of 11-op
// ============================================================
#define CHUNK 8
#define NCHUNK (Nc/CHUNK)         // 128
#define APAD 1028                 // %32==4 (conflict-free STS), 4B*APAD aligned for LDS.128

__global__ void __launch_bounds__(256,1) attn_kernel(const float* __restrict__ adj)
{
    extern __shared__ float sm[];
    float* Ks = sm;                       // [1024][16]
    float* Vs = sm + Nc*HDc;              // [1024][16]
    float* Abuf = sm + 2*Nc*HDc;          // 2 x [CHUNK][APAD]

    int bt = blockIdx.x >> 3;
    int h  = blockIdx.x & 7;
    int slab = bt*Hc + h;
    int t = threadIdx.x;

    // ---- load K,V slab (coalesced) ----
    const float* kg = g_k + (size_t)slab*Nc*HDc;
    const float* vg = g_v + (size_t)slab*Nc*HDc;
    #pragma unroll
    for (int i = t; i < Nc*HDc/4; i += 256) {
        ((float4*)Ks)[i] = ((const float4*)kg)[i];
        ((float4*)Vs)[i] = ((const float4*)vg)[i];
    }

    // ---- load q for my 4 rows (pre-scaled by log2e/4) ----
    int r0 = 4*t;
    f2_t q2[4][8];
    const float* qp = g_q + ((size_t)slab*Nc + r0)*HDc;
    #pragma unroll
    for (int rr = 0; rr < 4; ++rr)
        #pragma unroll
        for (int j = 0; j < 4; ++j) {
            float4 f = *(const float4*)(qp + rr*HDc + j*4);
            q2[rr][2*j]   = f2_pack(f.x, f.y);
            q2[rr][2*j+1] = f2_pack(f.z, f.w);
        }

    f2_t acc2[4][8];
    #pragma unroll
    for (int rr = 0; rr < 4; ++rr)
        #pragma unroll
        for (int j = 0; j < 8; ++j) acc2[rr][j] = 0ULL;
    float sum[4] = {0.f, 0.f, 0.f, 0.f};

    // adj base; per-thread fixed (row, colgroup) slot inside a chunk tile:
    // element e = it*256 + t  ->  row = e>>1, colgroup cq = e&1 (4 cols each)
    const float* ag = adj + (size_t)bt*Nc*Nc;
    float4 pf[8];
    #pragma unroll
    for (int it = 0; it < 8; ++it) {
        int e = it*256 + t;
        int r = e >> 1, cq = e & 1;
        pf[it] = *(const float4*)(ag + (size_t)r*Nc + 4*cq);
    }
    __syncthreads();   // K,V ready

    for (int chunk = 0; chunk < NCHUNK; ++chunk) {
        float* As = Abuf + (chunk & 1) * (CHUNK*APAD);

        // ---- store prefetched chunk transposed (conflict-free) ----
        #pragma unroll
        for (int it = 0; it < 8; ++it) {
            int e = it*256 + t;
            int r = e >> 1, cq = e & 1;
            As[(4*cq+0)*APAD + r] = pf[it].x;
            As[(4*cq+1)*APAD + r] = pf[it].y;
            As[(4*cq+2)*APAD + r] = pf[it].z;
            As[(4*cq+3)*APAD + r] = pf[it].w;
        }
        // ---- prefetch next chunk ----
        int nchunk = (chunk+1 < NCHUNK) ? (chunk+1) : 0;
        const float* agn = ag + nchunk*CHUNK;
        #pragma unroll
        for (int it = 0; it < 8; ++it) {
            int e = it*256 + t;
            int r = e >> 1, cq = e & 1;
            pf[it] = *(const float4*)(agn + (size_t)r*Nc + 4*cq);
        }
        __syncthreads();   // As writes visible; prior buffer reads complete

        int c0 = chunk*CHUNK;
        #pragma unroll 2
        for (int lc = 0; lc < CHUNK; ++lc) {
            int c = c0 + lc;
            const ulonglong2* kr = (const ulonglong2*)(Ks + c*HDc);
            ulonglong2 k0 = kr[0], k1 = kr[1], k2 = kr[2], k3 = kr[3];
            const ulonglong2* vr = (const ulonglong2*)(Vs + c*HDc);
            ulonglong2 v0 = vr[0], v1 = vr[1], v2 = vr[2], v3 = vr[3];
            float4 a4 = *(const float4*)(As + lc*APAD + r0);
            float aarr[4] = {a4.x, a4.y, a4.z, a4.w};

            #pragma unroll
            for (int rr = 0; rr < 4; ++rr) {
                // 9-op dot: two parallel chains
                f2_t d0 = f2_mul(q2[rr][0], k0.x);
                f2_t d1 = f2_mul(q2[rr][1], k0.y);
                d0 = f2_fma(q2[rr][2], k1.x, d0);
                d1 = f2_fma(q2[rr][3], k1.y, d1);
                d0 = f2_fma(q2[rr][4], k2.x, d0);
                d1 = f2_fma(q2[rr][5], k2.y, d1);
                d0 = f2_fma(q2[rr][6], k3.x, d0);
                d1 = f2_fma(q2[rr][7], k3.y, d1);
                d0 = f2_add(d0, d1);
                float lo, hi; f2_unpack(d0, lo, hi);
                float s = lo + hi;                 // log2-domain score

                float p = fast_ex2(s) * aarr[rr];  // MUFU pipe
                sum[rr] += p;
                f2_t pp = f2_pack(p, p);

                acc2[rr][0] = f2_fma(pp, v0.x, acc2[rr][0]);
                acc2[rr][1] = f2_fma(pp, v0.y, acc2[rr][1]);
                acc2[rr][2] = f2_fma(pp, v1.x, acc2[rr][2]);
                acc2[rr][3] = f2_fma(pp, v1.y, acc2[rr][3]);
                acc2[rr][4] = f2_fma(pp, v2.x, acc2[rr][4]);
                acc2[rr][5] = f2_fma(pp, v2.y, acc2[rr][5]);
                acc2[rr][6] = f2_fma(pp, v3.x, acc2[rr][6]);
                acc2[rr][7] = f2_fma(pp, v3.y, acc2[rr][7]);
            }
        }
        // no second barrier: double buffering separates writers/readers
    }

    // ---- write context ----
    #pragma unroll
    for (int rr = 0; rr < 4; ++rr) {
        float inv = 1.0f / sum[rr];
        float* outp = g_ctx + ((size_t)bt*Nc + r0 + rr)*Dc + h*HDc;
        #pragma unroll
        for (int j = 0; j < 4; ++j) {
            float lo0, hi0, lo1, hi1;
            f2_unpack(acc2[rr][2*j],   lo0, hi0);
            f2_unpack(acc2[rr][2*j+1], lo1, hi1);
            *(float4*)(outp + j*4) = make_float4(lo0*inv, hi0*inv, lo1*inv, hi1*inv);
        }
    }
}

// ============================================================
extern "C" void kernel_launch(void* const* d_in, const int* in_sizes, int n_in,
                              void* d_out, int out_size)
{
    const float* x   = (const float*)d_in[0];
    const float* adj = (const float*)d_in[1];
    const float* Wq  = (const float*)d_in[2];
    const float* bq  = (const float*)d_in[3];
    const float* Wk  = (const float*)d_in[4];
    const float* bk  = (const float*)d_in[5];
    const float* Wv  = (const float*)d_in[6];
    const float* bv  = (const float*)d_in[7];
    const float* Wo  = (const float*)d_in[8];
    const float* bo  = (const float*)d_in[9];
    float* out = (float*)d_out;

    const int smem_proj = 2 * 128 * 132 * sizeof(float);                    // 135168
    const int smem_attn = (2*Nc*HDc + 2*CHUNK*APAD) * sizeof(float);        // 196864
    cudaFuncSetAttribute(proj_qkv_kernel, cudaFuncAttributeMaxDynamicSharedMemorySize, smem_proj);
    cudaFuncSetAttribute(proj_o_kernel,   cudaFuncAttributeMaxDynamicSharedMemorySize, smem_proj);
    cudaFuncSetAttribute(attn_kernel,     cudaFuncAttributeMaxDynamicSharedMemorySize, smem_attn);

    dim3 gqkv(Mc/128, 3);
    proj_qkv_kernel<<<gqkv, 256, smem_proj>>>(x, Wq, bq, Wk, bk, Wv, bv);
    attn_kernel<<<BTc*Hc, 256, smem_attn>>>(adj);
    proj_o_kernel<<<Mc/128, 256, smem_proj>>>(Wo, bo, out);
}